// round 3
// baseline (speedup 1.0000x reference)
#include <cuda_runtime.h>
#include <cstdint>

#define N_NODES 50000
#define E_EDGES 800000
#define F_IN    128
#define F_OUT   64

// Scratch for support = (X @ W) * t  -- 12.8 MB, static device allocation.
__device__ float g_support[N_NODES * F_OUT];

// ---------------------------------------------------------------------------
// Kernel 1: GEMM  support[n][f] = (sum_k x[n][k] * W[k][f]) * t[n]
// Block: 256 threads, tile 64 rows x 64 cols (full F_OUT), 4x4 per thread.
// ---------------------------------------------------------------------------
#define TM 64
#define GEMM_THREADS 256

__global__ void __launch_bounds__(GEMM_THREADS)
gemm_scale_kernel(const float* __restrict__ x,
                  const float* __restrict__ t,
                  const float* __restrict__ weight)
{
    __shared__ float Ws[F_IN * F_OUT];   // 32 KB, layout [k][f]
    __shared__ float xs[TM * F_IN];      // 32 KB, layout [r][k]

    const int tid  = threadIdx.x;
    const int row0 = blockIdx.x * TM;

    // Load W (8192 floats) cooperatively
    #pragma unroll
    for (int i = tid; i < F_IN * F_OUT; i += GEMM_THREADS)
        Ws[i] = weight[i];

    // Load 64 rows of x (coalesced over k)
    for (int i = tid; i < TM * F_IN; i += GEMM_THREADS) {
        int r = i >> 7;          // local row
        int k = i & (F_IN - 1);
        int row = row0 + r;
        xs[i] = (row < N_NODES) ? x[row * F_IN + k] : 0.0f;
    }
    __syncthreads();

    const int cg = tid & 15;     // col group: cols 4*cg .. 4*cg+3
    const int rg = tid >> 4;     // row group: rows 4*rg .. 4*rg+3

    float acc[4][4];
    #pragma unroll
    for (int i = 0; i < 4; i++)
        #pragma unroll
        for (int j = 0; j < 4; j++)
            acc[i][j] = 0.0f;

    const float* xs0 = &xs[(rg * 4 + 0) * F_IN];
    const float* xs1 = &xs[(rg * 4 + 1) * F_IN];
    const float* xs2 = &xs[(rg * 4 + 2) * F_IN];
    const float* xs3 = &xs[(rg * 4 + 3) * F_IN];

    #pragma unroll 8
    for (int k = 0; k < F_IN; k++) {
        float4 wv = *(const float4*)&Ws[k * F_OUT + cg * 4];
        float xv0 = xs0[k];
        float xv1 = xs1[k];
        float xv2 = xs2[k];
        float xv3 = xs3[k];
        acc[0][0] += xv0 * wv.x; acc[0][1] += xv0 * wv.y;
        acc[0][2] += xv0 * wv.z; acc[0][3] += xv0 * wv.w;
        acc[1][0] += xv1 * wv.x; acc[1][1] += xv1 * wv.y;
        acc[1][2] += xv1 * wv.z; acc[1][3] += xv1 * wv.w;
        acc[2][0] += xv2 * wv.x; acc[2][1] += xv2 * wv.y;
        acc[2][2] += xv2 * wv.z; acc[2][3] += xv2 * wv.w;
        acc[3][0] += xv3 * wv.x; acc[3][1] += xv3 * wv.y;
        acc[3][2] += xv3 * wv.z; acc[3][3] += xv3 * wv.w;
    }

    #pragma unroll
    for (int i = 0; i < 4; i++) {
        int row = row0 + rg * 4 + i;
        if (row < N_NODES) {
            float tv = t[row];
            float4 v;
            v.x = acc[i][0] * tv;
            v.y = acc[i][1] * tv;
            v.z = acc[i][2] * tv;
            v.w = acc[i][3] * tv;
            *(float4*)&g_support[row * F_OUT + cg * 4] = v;
        }
    }
}

// ---------------------------------------------------------------------------
// Kernel 2: out[n][f] = bias[f]   (output is poisoned; seed with bias so the
// scatter can accumulate directly into it)
// ---------------------------------------------------------------------------
__global__ void bias_init_kernel(float* __restrict__ out,
                                 const float* __restrict__ bias,
                                 int total)
{
    int gid = blockIdx.x * blockDim.x + threadIdx.x;
    if (gid < total)
        out[gid] = bias[gid & (F_OUT - 1)];
}

// ---------------------------------------------------------------------------
// Kernel 3: scatter-add.  16 threads per edge, one float4 each.
// out[dst[e]][:] += support[src[e]][:] * edge_vals[e]
// NOTE: src/dst arrive as int32 (harness narrows int64 inputs).
// ---------------------------------------------------------------------------
__device__ __forceinline__ void red_add_v4(float* addr, float a, float b,
                                           float c, float d)
{
    asm volatile("red.global.add.v4.f32 [%0], {%1, %2, %3, %4};"
                 :: "l"(addr), "f"(a), "f"(b), "f"(c), "f"(d)
                 : "memory");
}

__global__ void __launch_bounds__(256)
scatter_kernel(const int* __restrict__ src,
               const int* __restrict__ dst,
               const float* __restrict__ edge_vals,
               float* __restrict__ out)
{
    int gid = blockIdx.x * blockDim.x + threadIdx.x;
    int e = gid >> 4;            // edge index
    int c = gid & 15;            // float4 chunk within the 64-feature row
    if (e >= E_EDGES) return;

    int s = __ldg(&src[e]);
    int d = __ldg(&dst[e]);
    float ev = __ldg(&edge_vals[e]);

    const float4* sp = (const float4*)&g_support[(size_t)s * F_OUT] + c;
    float4 v = __ldg(sp);

    red_add_v4(&out[(size_t)d * F_OUT + c * 4],
               v.x * ev, v.y * ev, v.z * ev, v.w * ev);
}

// ---------------------------------------------------------------------------
// Launch
// Inputs (metadata order): x, t, src, dst, edge_vals, weight, bias
// ---------------------------------------------------------------------------
extern "C" void kernel_launch(void* const* d_in, const int* in_sizes, int n_in,
                              void* d_out, int out_size)
{
    const float* x         = (const float*)d_in[0];
    const float* t         = (const float*)d_in[1];
    const int*   src       = (const int*)d_in[2];
    const int*   dst       = (const int*)d_in[3];
    const float* edge_vals = (const float*)d_in[4];
    const float* weight    = (const float*)d_in[5];
    const float* bias      = (const float*)d_in[6];
    float*       out       = (float*)d_out;

    // 1. support = (X @ W) * t
    int gemm_blocks = (N_NODES + TM - 1) / TM;          // 782
    gemm_scale_kernel<<<gemm_blocks, GEMM_THREADS>>>(x, t, weight);

    // 2. out = bias (broadcast)
    int total = N_NODES * F_OUT;
    bias_init_kernel<<<(total + 255) / 256, 256>>>(out, bias, total);

    // 3. scatter-add over edges
    long long sthreads = (long long)E_EDGES * 16;
    int sblocks = (int)((sthreads + 255) / 256);        // 50000
    scatter_kernel<<<sblocks, 256>>>(src, dst, edge_vals, out);
}

// round 4
// speedup vs baseline: 1.6528x; 1.6528x over previous
#include <cuda_runtime.h>
#include <cstdint>

#define N_NODES 50000
#define E_EDGES 800000
#define F_IN    128
#define F_OUT   64

// Scratch for support = (X @ W) * t  -- 12.8 MB, static device allocation.
__device__ float g_support[N_NODES * F_OUT];

// ---------------------------------------------------------------------------
// Kernel 1: GEMM  support[n][f] = (sum_k x[n][k] * W[k][f]) * t[n]
// Tile 128 rows x 64 cols (full F_OUT), BK=32, 256 threads, 8x4 reg tile.
// W fully resident in smem; x K-chunks double-buffered with reg prefetch.
// ---------------------------------------------------------------------------
#define BM 128
#define BK 32
#define XS_STRIDE 36            // 32 + 4 pad, keeps 16B alignment
#define GEMM_THREADS 256

__global__ void __launch_bounds__(GEMM_THREADS)
gemm_scale_kernel(const float* __restrict__ x,
                  const float* __restrict__ t,
                  const float* __restrict__ weight)
{
    __shared__ float Ws[F_IN * F_OUT];              // 32 KB, [k][f]
    __shared__ float xs[2][BM * XS_STRIDE];         // 2 x 18 KB

    const int tid  = threadIdx.x;
    const int row0 = blockIdx.x * BM;

    // Load full W (8192 floats = 512 float4) cooperatively
    {
        const float4* wg = (const float4*)weight;
        float4* wsv = (float4*)Ws;
        #pragma unroll
        for (int i = 0; i < (F_IN * F_OUT / 4) / GEMM_THREADS; i++)
            wsv[tid + i * GEMM_THREADS] = wg[tid + i * GEMM_THREADS];
    }

    // x chunk loader: 128 rows x 32 floats = 1024 float4, 4 per thread.
    // idx = tid + p*256 ; f4 = idx & 7 ; row = idx >> 3
    auto load_chunk = [&](int kc, float4* pref) {
        #pragma unroll
        for (int p = 0; p < 4; p++) {
            int idx = tid + p * GEMM_THREADS;
            int f4  = idx & 7;
            int row = idx >> 3;
            int grow = row0 + row;
            if (grow < N_NODES)
                pref[p] = *(const float4*)&x[(size_t)grow * F_IN + kc * BK + f4 * 4];
            else
                pref[p] = make_float4(0.f, 0.f, 0.f, 0.f);
        }
    };
    auto store_chunk = [&](int buf, const float4* pref) {
        #pragma unroll
        for (int p = 0; p < 4; p++) {
            int idx = tid + p * GEMM_THREADS;
            int f4  = idx & 7;
            int row = idx >> 3;
            *(float4*)&xs[buf][row * XS_STRIDE + f4 * 4] = pref[p];
        }
    };

    float4 pref[4];
    load_chunk(0, pref);
    store_chunk(0, pref);
    __syncthreads();

    const int rg = tid >> 4;    // 0..15 -> rows rg*8 .. rg*8+7
    const int cg = tid & 15;    // cols cg*4 .. cg*4+3

    float acc[8][4];
    #pragma unroll
    for (int i = 0; i < 8; i++)
        #pragma unroll
        for (int j = 0; j < 4; j++)
            acc[i][j] = 0.0f;

    const int NCHUNK = F_IN / BK;   // 4
    #pragma unroll
    for (int kc = 0; kc < NCHUNK; kc++) {
        if (kc + 1 < NCHUNK)
            load_chunk(kc + 1, pref);

        const float* xb = &xs[kc & 1][0];
        #pragma unroll
        for (int kq = 0; kq < BK / 4; kq++) {
            // 4 W rows (k = kc*32 + kq*4 + j), 4 cols each
            float4 wv0 = *(const float4*)&Ws[(kc * BK + kq * 4 + 0) * F_OUT + cg * 4];
            float4 wv1 = *(const float4*)&Ws[(kc * BK + kq * 4 + 1) * F_OUT + cg * 4];
            float4 wv2 = *(const float4*)&Ws[(kc * BK + kq * 4 + 2) * F_OUT + cg * 4];
            float4 wv3 = *(const float4*)&Ws[(kc * BK + kq * 4 + 3) * F_OUT + cg * 4];
            #pragma unroll
            for (int i = 0; i < 8; i++) {
                float4 xv = *(const float4*)&xb[(rg * 8 + i) * XS_STRIDE + kq * 4];
                acc[i][0] += xv.x * wv0.x + xv.y * wv1.x + xv.z * wv2.x + xv.w * wv3.x;
                acc[i][1] += xv.x * wv0.y + xv.y * wv1.y + xv.z * wv2.y + xv.w * wv3.y;
                acc[i][2] += xv.x * wv0.z + xv.y * wv1.z + xv.z * wv2.z + xv.w * wv3.z;
                acc[i][3] += xv.x * wv0.w + xv.y * wv1.w + xv.z * wv2.w + xv.w * wv3.w;
            }
        }

        __syncthreads();
        if (kc + 1 < NCHUNK) {
            store_chunk((kc + 1) & 1, pref);
            __syncthreads();
        }
    }

    #pragma unroll
    for (int i = 0; i < 8; i++) {
        int row = row0 + rg * 8 + i;
        if (row < N_NODES) {
            float tv = __ldg(&t[row]);
            float4 v;
            v.x = acc[i][0] * tv;
            v.y = acc[i][1] * tv;
            v.z = acc[i][2] * tv;
            v.w = acc[i][3] * tv;
            *(float4*)&g_support[(size_t)row * F_OUT + cg * 4] = v;
        }
    }
}

// ---------------------------------------------------------------------------
// Kernel 2: out[n][f] = bias[f]  (float4 per thread)
// ---------------------------------------------------------------------------
__global__ void bias_init_kernel(float* __restrict__ out,
                                 const float* __restrict__ bias,
                                 int total4)
{
    int gid = blockIdx.x * blockDim.x + threadIdx.x;
    if (gid < total4) {
        int f4 = gid & 15;      // float4 index within 64-feature row
        float4 b = *(const float4*)&bias[f4 * 4];
        ((float4*)out)[gid] = b;
    }
}

// ---------------------------------------------------------------------------
// Kernel 3: scatter-add.  16 threads per edge, one float4 each.
// out[dst[e]][:] += support[src[e]][:] * edge_vals[e]
// src/dst arrive as int32 (harness narrows int64 inputs).
// ---------------------------------------------------------------------------
__device__ __forceinline__ void red_add_v4(float* addr, float a, float b,
                                           float c, float d)
{
    asm volatile("red.global.add.v4.f32 [%0], {%1, %2, %3, %4};"
                 :: "l"(addr), "f"(a), "f"(b), "f"(c), "f"(d)
                 : "memory");
}

__global__ void __launch_bounds__(256)
scatter_kernel(const int* __restrict__ src,
               const int* __restrict__ dst,
               const float* __restrict__ edge_vals,
               float* __restrict__ out)
{
    int gid = blockIdx.x * blockDim.x + threadIdx.x;
    int e = gid >> 4;            // edge index
    int c = gid & 15;            // float4 chunk within the 64-feature row
    if (e >= E_EDGES) return;

    int s = __ldg(&src[e]);
    int d = __ldg(&dst[e]);
    float ev = __ldg(&edge_vals[e]);

    const float4* sp = (const float4*)&g_support[(size_t)s * F_OUT] + c;
    float4 v = __ldg(sp);

    red_add_v4(&out[(size_t)d * F_OUT + c * 4],
               v.x * ev, v.y * ev, v.z * ev, v.w * ev);
}

// ---------------------------------------------------------------------------
// Launch.  Inputs (metadata order): x, t, src, dst, edge_vals, weight, bias
// ---------------------------------------------------------------------------
extern "C" void kernel_launch(void* const* d_in, const int* in_sizes, int n_in,
                              void* d_out, int out_size)
{
    const float* x         = (const float*)d_in[0];
    const float* t         = (const float*)d_in[1];
    const int*   src       = (const int*)d_in[2];
    const int*   dst       = (const int*)d_in[3];
    const float* edge_vals = (const float*)d_in[4];
    const float* weight    = (const float*)d_in[5];
    const float* bias      = (const float*)d_in[6];
    float*       out       = (float*)d_out;

    // 1. support = (X @ W) * t
    int gemm_blocks = (N_NODES + BM - 1) / BM;          // 391
    gemm_scale_kernel<<<gemm_blocks, GEMM_THREADS>>>(x, t, weight);

    // 2. out = bias (broadcast, float4)
    int total4 = N_NODES * F_OUT / 4;
    bias_init_kernel<<<(total4 + 255) / 256, 256>>>(out, bias, total4);

    // 3. scatter-add over edges
    long long sthreads = (long long)E_EDGES * 16;
    int sblocks = (int)((sthreads + 255) / 256);        // 50000
    scatter_kernel<<<sblocks, 256>>>(src, dst, edge_vals, out);
}

// round 6
// speedup vs baseline: 1.9294x; 1.1674x over previous
#include <cuda_runtime.h>
#include <cuda_bf16.h>
#include <cstdint>

#define N_NODES 50000
#define E_EDGES 800000
#define F_IN    128
#define F_OUT   64

// Scratch for support = (X @ W) * t  -- 12.8 MB, static device allocation.
__device__ float g_support[N_NODES * F_OUT];

// ===========================================================================
// Kernel 1: GEMM via mma.sync (HMMA) with bf16 hi/lo 3-term split.
// Tile: M=128 per CTA, N=64 (full F_OUT), K=128 (full F_IN).
// 8 warps; warp w computes rows 16w..16w+15 x all 64 cols.
// ===========================================================================
#define GT 256

// smem layout (bytes). Rows padded to 272B (136 bf16) -> conflict-free ldmatrix.
#define ASTR 272
#define SM_AHI 0
#define SM_ALO (SM_AHI + 128 * ASTR)     // 34816
#define SM_BHI (SM_ALO + 128 * ASTR)     // 69632
#define SM_BLO (SM_BHI + 64 * ASTR)      // 87040
#define SM_TOTAL (SM_BLO + 64 * ASTR)    // 104448

__device__ __forceinline__ uint32_t smem_u32(const void* p) {
    uint32_t a;
    asm("{ .reg .u64 tmp; cvta.to.shared.u64 tmp, %1; cvt.u32.u64 %0, tmp; }"
        : "=r"(a) : "l"(p));
    return a;
}

__device__ __forceinline__ void ldmatrix_x4(uint32_t* r, uint32_t addr) {
    asm volatile("ldmatrix.sync.aligned.m8n8.x4.shared.b16 {%0,%1,%2,%3}, [%4];"
                 : "=r"(r[0]), "=r"(r[1]), "=r"(r[2]), "=r"(r[3]) : "r"(addr));
}

__device__ __forceinline__ void mma_bf16(float* d, const uint32_t* a,
                                         const uint32_t* b) {
    asm volatile(
        "mma.sync.aligned.m16n8k16.row.col.f32.bf16.bf16.f32 "
        "{%0,%1,%2,%3}, {%4,%5,%6,%7}, {%8,%9}, {%0,%1,%2,%3};"
        : "+f"(d[0]), "+f"(d[1]), "+f"(d[2]), "+f"(d[3])
        : "r"(a[0]), "r"(a[1]), "r"(a[2]), "r"(a[3]), "r"(b[0]), "r"(b[1]));
}

__global__ void __launch_bounds__(GT)
gemm_tc_kernel(const float* __restrict__ x,
               const float* __restrict__ t,
               const float* __restrict__ weight)
{
    extern __shared__ char smem[];
    const uint32_t sb = smem_u32(smem);
    const int tid  = threadIdx.x;
    const int wid  = tid >> 5;
    const int lane = tid & 31;
    const int row0 = blockIdx.x * 128;

    // ---- stage W^T (hi/lo) : B[f][k], scalar (one-time 8K elements)
    for (int i = tid; i < F_IN * F_OUT; i += GT) {
        int f = i & 63;            // n
        int k = i >> 6;            // k
        float v = weight[i];       // weight[k][f]
        __nv_bfloat16 h = __float2bfloat16(v);
        __nv_bfloat16 l = __float2bfloat16(v - __bfloat162float(h));
        *(__nv_bfloat16*)(smem + SM_BHI + f * ASTR + k * 2) = h;
        *(__nv_bfloat16*)(smem + SM_BLO + f * ASTR + k * 2) = l;
    }

    // ---- stage x tile (hi/lo): 128 rows x 128 k, float4-coalesced loads
    #pragma unroll
    for (int p = 0; p < 16; p++) {
        int idx = tid + p * GT;        // 0..4095
        int k4  = idx & 31;            // float4 within row
        int row = idx >> 5;
        int grow = row0 + row;
        float4 v = (grow < N_NODES)
                 ? *(const float4*)&x[(size_t)grow * F_IN + k4 * 4]
                 : make_float4(0.f, 0.f, 0.f, 0.f);
        __nv_bfloat162 h0 = __floats2bfloat162_rn(v.x, v.y);
        __nv_bfloat162 h1 = __floats2bfloat162_rn(v.z, v.w);
        float lx = v.x - __bfloat162float(__low2bfloat16(h0));
        float ly = v.y - __bfloat162float(__high2bfloat16(h0));
        float lz = v.z - __bfloat162float(__low2bfloat16(h1));
        float lw = v.w - __bfloat162float(__high2bfloat16(h1));
        __nv_bfloat162 l0 = __floats2bfloat162_rn(lx, ly);
        __nv_bfloat162 l1 = __floats2bfloat162_rn(lz, lw);
        uint2 hv, lv;
        hv.x = *(uint32_t*)&h0; hv.y = *(uint32_t*)&h1;
        lv.x = *(uint32_t*)&l0; lv.y = *(uint32_t*)&l1;
        *(uint2*)(smem + SM_AHI + row * ASTR + k4 * 8) = hv;
        *(uint2*)(smem + SM_ALO + row * ASTR + k4 * 8) = lv;
    }
    __syncthreads();

    // ---- mainloop: warp computes rows 16*wid..+15, all 64 cols
    float acc[8][4];
    #pragma unroll
    for (int j = 0; j < 8; j++)
        #pragma unroll
        for (int q = 0; q < 4; q++)
            acc[j][q] = 0.0f;

    const int wrow = wid * 16;
    const int afrag = lane >> 3;       // 0..3
    const int arow  = lane & 7;

    #pragma unroll
    for (int kk = 0; kk < 8; kk++) {
        // A frags: order (r0-7,k0-7)(r8-15,k0-7)(r0-7,k8-15)(r8-15,k8-15)
        uint32_t a_addr_off = (uint32_t)((wrow + (afrag & 1) * 8 + arow) * ASTR
                                         + (kk * 16 + (afrag >> 1) * 8) * 2);
        uint32_t ahi[4], alo[4];
        ldmatrix_x4(ahi, sb + SM_AHI + a_addr_off);
        ldmatrix_x4(alo, sb + SM_ALO + a_addr_off);

        #pragma unroll
        for (int j2 = 0; j2 < 4; j2++) {    // pairs of n-tiles
            // B frags: (n 8j2*2.., k0-7)(.., k8-15)(next n-tile k0-7)(k8-15)
            uint32_t b_addr_off = (uint32_t)((j2 * 16 + (afrag >> 1) * 8 + arow) * ASTR
                                             + (kk * 16 + (afrag & 1) * 8) * 2);
            uint32_t bhi[4], blo[4];
            ldmatrix_x4(bhi, sb + SM_BHI + b_addr_off);
            ldmatrix_x4(blo, sb + SM_BLO + b_addr_off);

            mma_bf16(acc[j2 * 2 + 0], ahi, bhi + 0);
            mma_bf16(acc[j2 * 2 + 1], ahi, bhi + 2);
            mma_bf16(acc[j2 * 2 + 0], ahi, blo + 0);
            mma_bf16(acc[j2 * 2 + 1], ahi, blo + 2);
            mma_bf16(acc[j2 * 2 + 0], alo, bhi + 0);
            mma_bf16(acc[j2 * 2 + 1], alo, bhi + 2);
        }
    }

    // ---- epilogue: d-frag rows = wrow + lane/4 (+8), cols = j*8 + (lane%4)*2
    int r0 = row0 + wrow + (lane >> 2);
    int c0 = (lane & 3) * 2;
    float tv0 = 0.f, tv1 = 0.f;
    if (r0 < N_NODES)     tv0 = __ldg(&t[r0]);
    if (r0 + 8 < N_NODES) tv1 = __ldg(&t[r0 + 8]);

    #pragma unroll
    for (int j = 0; j < 8; j++) {
        if (r0 < N_NODES) {
            float2 v = make_float2(acc[j][0] * tv0, acc[j][1] * tv0);
            *(float2*)&g_support[(size_t)r0 * F_OUT + j * 8 + c0] = v;
        }
        if (r0 + 8 < N_NODES) {
            float2 v = make_float2(acc[j][2] * tv1, acc[j][3] * tv1);
            *(float2*)&g_support[(size_t)(r0 + 8) * F_OUT + j * 8 + c0] = v;
        }
    }
}

// ---------------------------------------------------------------------------
// Kernel 2: out[n][f] = bias[f]  (float4 per thread)
// ---------------------------------------------------------------------------
__global__ void bias_init_kernel(float* __restrict__ out,
                                 const float* __restrict__ bias,
                                 int total4)
{
    int gid = blockIdx.x * blockDim.x + threadIdx.x;
    if (gid < total4) {
        int f4 = gid & 15;
        float4 b = *(const float4*)&bias[f4 * 4];
        ((float4*)out)[gid] = b;
    }
}

// ---------------------------------------------------------------------------
// Kernel 3: scatter-add.  16 threads per edge, one float4 each.
// ---------------------------------------------------------------------------
__device__ __forceinline__ void red_add_v4(float* addr, float a, float b,
                                           float c, float d)
{
    asm volatile("red.global.add.v4.f32 [%0], {%1, %2, %3, %4};"
                 :: "l"(addr), "f"(a), "f"(b), "f"(c), "f"(d)
                 : "memory");
}

__global__ void __launch_bounds__(256)
scatter_kernel(const int* __restrict__ src,
               const int* __restrict__ dst,
               const float* __restrict__ edge_vals,
               float* __restrict__ out)
{
    int gid = blockIdx.x * blockDim.x + threadIdx.x;
    int e = gid >> 4;
    int c = gid & 15;
    if (e >= E_EDGES) return;

    int s = __ldg(&src[e]);
    int d = __ldg(&dst[e]);
    float ev = __ldg(&edge_vals[e]);

    const float4* sp = (const float4*)&g_support[(size_t)s * F_OUT] + c;
    float4 v = __ldg(sp);

    red_add_v4(&out[(size_t)d * F_OUT + c * 4],
               v.x * ev, v.y * ev, v.z * ev, v.w * ev);
}

// ---------------------------------------------------------------------------
// Launch.  Inputs (metadata order): x, t, src, dst, edge_vals, weight, bias
// ---------------------------------------------------------------------------
extern "C" void kernel_launch(void* const* d_in, const int* in_sizes, int n_in,
                              void* d_out, int out_size)
{
    const float* x         = (const float*)d_in[0];
    const float* t         = (const float*)d_in[1];
    const int*   src       = (const int*)d_in[2];
    const int*   dst       = (const int*)d_in[3];
    const float* edge_vals = (const float*)d_in[4];
    const float* weight    = (const float*)d_in[5];
    const float* bias      = (const float*)d_in[6];
    float*       out       = (float*)d_out;

    static int smem_set = 0;
    if (!smem_set) {
        cudaFuncSetAttribute(gemm_tc_kernel,
                             cudaFuncAttributeMaxDynamicSharedMemorySize,
                             SM_TOTAL);
        smem_set = 1;
    }

    // 1. support = (X @ W) * t   (HMMA, bf16 hi/lo 3-term split)
    int gemm_blocks = (N_NODES + 127) / 128;            // 391
    gemm_tc_kernel<<<gemm_blocks, GT, SM_TOTAL>>>(x, t, weight);

    // 2. out = bias (broadcast, float4)
    int total4 = N_NODES * F_OUT / 4;
    bias_init_kernel<<<(total4 + 255) / 256, 256>>>(out, bias, total4);

    // 3. scatter-add over edges
    long long sthreads = (long long)E_EDGES * 16;
    int sblocks = (int)((sthreads + 255) / 256);        // 50000
    scatter_kernel<<<sblocks, 256>>>(src, dst, edge_vals, out);
}

// round 7
// speedup vs baseline: 2.0688x; 1.0722x over previous
#include <cuda_runtime.h>
#include <cuda_bf16.h>
#include <cstdint>

#define N_NODES 50000
#define E_EDGES 800000
#define F_IN    128
#define F_OUT   64

// Scratch: support = (X @ W) * t  -- 12.8 MB static.
__device__ float g_support[N_NODES * F_OUT];
// Precomputed W^T hi/lo split, layout [f][k] (k contiguous), bf16.
__device__ __nv_bfloat16 g_whi[F_OUT * F_IN];
__device__ __nv_bfloat16 g_wlo[F_OUT * F_IN];

// ===========================================================================
// Kernel 0: split weight[k][f] (fp32) -> g_whi/g_wlo[f][k] (bf16)
// ===========================================================================
__global__ void wsplit_kernel(const float* __restrict__ weight)
{
    int i = blockIdx.x * blockDim.x + threadIdx.x;   // 0..8191
    if (i < F_IN * F_OUT) {
        int f = i & 63;
        int k = i >> 6;
        float v = weight[i];                         // weight[k][f]
        __nv_bfloat16 h = __float2bfloat16(v);
        __nv_bfloat16 l = __float2bfloat16(v - __bfloat162float(h));
        g_whi[f * F_IN + k] = h;
        g_wlo[f * F_IN + k] = l;
    }
}

// ===========================================================================
// Kernel 1: GEMM via mma.sync, A loaded gmem->regs (hi/lo split in regs),
// B (W^T) from precomputed bf16 via smem + ldmatrix. M=128/CTA, 8 warps.
// Bias-init of `out` folded into the epilogue.
// ===========================================================================
#define GT 256
#define ASTR 272                       // padded smem row stride (bytes)
#define SM_BHI 0
#define SM_BLO (SM_BHI + 64 * ASTR)    // 17408
#define SM_TOTAL (SM_BLO + 64 * ASTR)  // 34816

__device__ __forceinline__ uint32_t smem_u32(const void* p) {
    uint32_t a;
    asm("{ .reg .u64 tmp; cvta.to.shared.u64 tmp, %1; cvt.u32.u64 %0, tmp; }"
        : "=r"(a) : "l"(p));
    return a;
}

__device__ __forceinline__ void ldmatrix_x4(uint32_t* r, uint32_t addr) {
    asm volatile("ldmatrix.sync.aligned.m8n8.x4.shared.b16 {%0,%1,%2,%3}, [%4];"
                 : "=r"(r[0]), "=r"(r[1]), "=r"(r[2]), "=r"(r[3]) : "r"(addr));
}

__device__ __forceinline__ void mma_bf16(float* d, const uint32_t* a,
                                         const uint32_t* b) {
    asm volatile(
        "mma.sync.aligned.m16n8k16.row.col.f32.bf16.bf16.f32 "
        "{%0,%1,%2,%3}, {%4,%5,%6,%7}, {%8,%9}, {%0,%1,%2,%3};"
        : "+f"(d[0]), "+f"(d[1]), "+f"(d[2]), "+f"(d[3])
        : "r"(a[0]), "r"(a[1]), "r"(a[2]), "r"(a[3]), "r"(b[0]), "r"(b[1]));
}

__device__ __forceinline__ uint32_t pack_hi(float2 v) {
    __nv_bfloat162 h = __floats2bfloat162_rn(v.x, v.y);
    return *(uint32_t*)&h;
}
__device__ __forceinline__ uint32_t pack_lo(float2 v) {
    __nv_bfloat162 h = __floats2bfloat162_rn(v.x, v.y);
    float rx = v.x - __bfloat162float(__low2bfloat16(h));
    float ry = v.y - __bfloat162float(__high2bfloat16(h));
    __nv_bfloat162 l = __floats2bfloat162_rn(rx, ry);
    return *(uint32_t*)&l;
}

__global__ void __launch_bounds__(GT, 3)
gemm_tc_kernel(const float* __restrict__ x,
               const float* __restrict__ t,
               const float* __restrict__ bias,
               float* __restrict__ out)
{
    extern __shared__ char smem[];
    const uint32_t sb = smem_u32(smem);
    const int tid  = threadIdx.x;
    const int wid  = tid >> 5;
    const int lane = tid & 31;
    const int row0 = blockIdx.x * 128;

    // ---- stage B (hi/lo) from precomputed globals: 64 rows x 128 bf16 each
    {
        const uint4* srcH = (const uint4*)g_whi;
        const uint4* srcL = (const uint4*)g_wlo;
        #pragma unroll
        for (int i = tid; i < 1024; i += GT) {       // 1024 uint4 per matrix
            int row = i >> 4;
            int q   = i & 15;
            *(uint4*)(smem + SM_BHI + row * ASTR + q * 16) = srcH[row * 16 + q];
            *(uint4*)(smem + SM_BLO + row * ASTR + q * 16) = srcL[row * 16 + q];
        }
    }
    __syncthreads();

    // ---- A addressing: direct gmem float2 loads in mma fragment layout
    const int g   = lane >> 2;
    const int tig = lane & 3;
    const int r0g = row0 + wid * 16 + g;       // rows for a0/a2
    const int r1g = r0g + 8;                   // rows for a1/a3
    const bool v0 = r0g < N_NODES;
    const bool v1 = r1g < N_NODES;
    const float2* p0 = (const float2*)&x[(size_t)r0g * F_IN];
    const float2* p1 = (const float2*)&x[(size_t)r1g * F_IN];
    const float2 z2 = make_float2(0.f, 0.f);

    float acc[8][4];
    #pragma unroll
    for (int j = 0; j < 8; j++)
        #pragma unroll
        for (int q = 0; q < 4; q++)
            acc[j][q] = 0.0f;

    const int afrag = lane >> 3;
    const int arow  = lane & 7;

    // prefetch kk=0
    float2 c00 = v0 ? p0[tig]     : z2;   // (g,   k0)
    float2 c10 = v1 ? p1[tig]     : z2;   // (g+8, k0)
    float2 c01 = v0 ? p0[tig + 4] : z2;   // (g,   k0+8)
    float2 c11 = v1 ? p1[tig + 4] : z2;   // (g+8, k0+8)

    #pragma unroll
    for (int kk = 0; kk < 8; kk++) {
        float2 n00, n10, n01, n11;
        if (kk < 7) {
            int o = (kk + 1) * 8 + tig;
            n00 = v0 ? p0[o]     : z2;
            n10 = v1 ? p1[o]     : z2;
            n01 = v0 ? p0[o + 4] : z2;
            n11 = v1 ? p1[o + 4] : z2;
        }

        uint32_t ahi[4], alo[4];
        ahi[0] = pack_hi(c00); alo[0] = pack_lo(c00);
        ahi[1] = pack_hi(c10); alo[1] = pack_lo(c10);
        ahi[2] = pack_hi(c01); alo[2] = pack_lo(c01);
        ahi[3] = pack_hi(c11); alo[3] = pack_lo(c11);

        #pragma unroll
        for (int j2 = 0; j2 < 4; j2++) {
            uint32_t b_off = (uint32_t)((j2 * 16 + (afrag >> 1) * 8 + arow) * ASTR
                                        + (kk * 16 + (afrag & 1) * 8) * 2);
            uint32_t bhi[4], blo[4];
            ldmatrix_x4(bhi, sb + SM_BHI + b_off);
            ldmatrix_x4(blo, sb + SM_BLO + b_off);

            mma_bf16(acc[j2 * 2 + 0], ahi, bhi + 0);
            mma_bf16(acc[j2 * 2 + 1], ahi, bhi + 2);
            mma_bf16(acc[j2 * 2 + 0], ahi, blo + 0);
            mma_bf16(acc[j2 * 2 + 1], ahi, blo + 2);
            mma_bf16(acc[j2 * 2 + 0], alo, bhi + 0);
            mma_bf16(acc[j2 * 2 + 1], alo, bhi + 2);
        }

        c00 = n00; c10 = n10; c01 = n01; c11 = n11;
    }

    // ---- epilogue: scale by t, store support
    int r0 = row0 + wid * 16 + (lane >> 2);
    int c0 = (lane & 3) * 2;
    float tv0 = 0.f, tv1 = 0.f;
    if (r0 < N_NODES)     tv0 = __ldg(&t[r0]);
    if (r0 + 8 < N_NODES) tv1 = __ldg(&t[r0 + 8]);

    #pragma unroll
    for (int j = 0; j < 8; j++) {
        if (r0 < N_NODES) {
            float2 v = make_float2(acc[j][0] * tv0, acc[j][1] * tv0);
            *(float2*)&g_support[(size_t)r0 * F_OUT + j * 8 + c0] = v;
        }
        if (r0 + 8 < N_NODES) {
            float2 v = make_float2(acc[j][2] * tv1, acc[j][3] * tv1);
            *(float2*)&g_support[(size_t)(r0 + 8) * F_OUT + j * 8 + c0] = v;
        }
    }

    // ---- folded bias init: out[n][f] = bias[f]  (grid-stride float4)
    {
        const int total4 = N_NODES * F_OUT / 4;            // 800000
        const int stride = gridDim.x * GT;
        float4* out4 = (float4*)out;
        for (int i = blockIdx.x * GT + tid; i < total4; i += stride) {
            float4 b = *(const float4*)&bias[(i & 15) * 4];
            out4[i] = b;
        }
    }
}

// ---------------------------------------------------------------------------
// Kernel 3: scatter-add.  16 threads per edge, one float4 each.
// ---------------------------------------------------------------------------
__device__ __forceinline__ void red_add_v4(float* addr, float a, float b,
                                           float c, float d)
{
    asm volatile("red.global.add.v4.f32 [%0], {%1, %2, %3, %4};"
                 :: "l"(addr), "f"(a), "f"(b), "f"(c), "f"(d)
                 : "memory");
}

__global__ void __launch_bounds__(256)
scatter_kernel(const int* __restrict__ src,
               const int* __restrict__ dst,
               const float* __restrict__ edge_vals,
               float* __restrict__ out)
{
    int gid = blockIdx.x * blockDim.x + threadIdx.x;
    int e = gid >> 4;
    int c = gid & 15;
    if (e >= E_EDGES) return;

    int s = __ldg(&src[e]);
    int d = __ldg(&dst[e]);
    float ev = __ldg(&edge_vals[e]);

    const float4* sp = (const float4*)&g_support[(size_t)s * F_OUT] + c;
    float4 v = __ldg(sp);

    red_add_v4(&out[(size_t)d * F_OUT + c * 4],
               v.x * ev, v.y * ev, v.z * ev, v.w * ev);
}

// ---------------------------------------------------------------------------
// Launch.  Inputs (metadata order): x, t, src, dst, edge_vals, weight, bias
// ---------------------------------------------------------------------------
extern "C" void kernel_launch(void* const* d_in, const int* in_sizes, int n_in,
                              void* d_out, int out_size)
{
    const float* x         = (const float*)d_in[0];
    const float* t         = (const float*)d_in[1];
    const int*   src       = (const int*)d_in[2];
    const int*   dst       = (const int*)d_in[3];
    const float* edge_vals = (const float*)d_in[4];
    const float* weight    = (const float*)d_in[5];
    const float* bias      = (const float*)d_in[6];
    float*       out       = (float*)d_out;

    cudaFuncSetAttribute(gemm_tc_kernel,
                         cudaFuncAttributeMaxDynamicSharedMemorySize, SM_TOTAL);

    // 0. split W into bf16 hi/lo (tiny)
    wsplit_kernel<<<(F_IN * F_OUT + 255) / 256, 256>>>(weight);

    // 1. support = (X @ W) * t  + bias-init of out (folded)
    int gemm_blocks = (N_NODES + 127) / 128;            // 391
    gemm_tc_kernel<<<gemm_blocks, GT, SM_TOTAL>>>(x, t, bias, out);

    // 2. scatter-add over edges
    long long sthreads = (long long)E_EDGES * 16;
    int sblocks = (int)((sthreads + 255) / 256);        // 50000
    scatter_kernel<<<sblocks, 256>>>(src, dst, edge_vals, out);
}